// round 4
// baseline (speedup 1.0000x reference)
#include <cuda_runtime.h>
#include <cuda_bf16.h>
#include <math.h>
#include <stdint.h>

#define NPED  128
#define HD    64
#define NOUT  64
#define NROWS 4096
#define YC    4096      // Y columns = 64 cells * 64 out

// ---- scratch (no allocs allowed) ----
__device__ float g_Y[(size_t)NROWS * YC];                      // 64 MB
__device__ __align__(256) __nv_bfloat16 g_Wh[64 * YC];         // Wr hi: [h][c*64+o]
__device__ __align__(256) __nv_bfloat16 g_Wl[64 * YC];         // Wr lo
__device__ __align__(256) __nv_bfloat16 g_Hh[NROWS * HD];      // hs hi
__device__ __align__(256) __nv_bfloat16 g_Hl[NROWS * HD];      // hs lo
__device__ float g_part[128 * 2 * NOUT];                       // BN partials
__device__ float g_scale[NOUT];
__device__ float g_shift[NOUT];

// ---------------- helpers ----------------
__device__ __forceinline__ uint32_t smem_u32(const void* p) {
    uint32_t a;
    asm("{ .reg .u64 t; cvta.to.shared.u64 t, %1; cvt.u32.u64 %0, t; }" : "=r"(a) : "l"(p));
    return a;
}
__device__ __forceinline__ void ldsm_x4(uint32_t* a, uint32_t addr) {
    asm volatile("ldmatrix.sync.aligned.m8n8.x4.shared.b16 {%0,%1,%2,%3}, [%4];"
                 : "=r"(a[0]), "=r"(a[1]), "=r"(a[2]), "=r"(a[3]) : "r"(addr));
}
__device__ __forceinline__ void ldsm_x2t(uint32_t* b, uint32_t addr) {
    asm volatile("ldmatrix.sync.aligned.m8n8.x2.trans.shared.b16 {%0,%1}, [%2];"
                 : "=r"(b[0]), "=r"(b[1]) : "r"(addr));
}
__device__ __forceinline__ void mma16816(float* d, const uint32_t* a, const uint32_t* b) {
    asm volatile("mma.sync.aligned.m16n8k16.row.col.f32.bf16.bf16.f32 "
                 "{%0,%1,%2,%3}, {%4,%5,%6,%7}, {%8,%9}, {%0,%1,%2,%3};"
                 : "+f"(d[0]), "+f"(d[1]), "+f"(d[2]), "+f"(d[3])
                 : "r"(a[0]), "r"(a[1]), "r"(a[2]), "r"(a[3]), "r"(b[0]), "r"(b[1]));
}
__device__ __forceinline__ uint32_t pack2(__nv_bfloat16 x, __nv_bfloat16 y) {
    return (uint32_t)__bfloat16_as_ushort(x) | ((uint32_t)__bfloat16_as_ushort(y) << 16);
}

// ---------------------------------------------------------------------------
// W prep: Wr[h][c*64+o] = W[c*64+h][o], split bf16 hi/lo. Coalesced read.
// ---------------------------------------------------------------------------
__global__ void wprep_kernel(const float* __restrict__ W) {
    const int e = blockIdx.x * 256 + threadIdx.x;   // 262144 total
    const float v = W[e];
    const __nv_bfloat16 hi = __float2bfloat16(v);
    const float lo = v - __bfloat162float(hi);
    const int widx = ((e >> 6) & 63) * YC + (e >> 12) * 64 + (e & 63);
    g_Wh[widx] = hi;
    g_Wl[widx] = __float2bfloat16(lo);
}

// ---------------------------------------------------------------------------
// hs prep: split fp32 -> bf16 hi/lo, row-major (swizzled at smem-load time).
// ---------------------------------------------------------------------------
__global__ void hprep_kernel(const float* __restrict__ hs) {
    const int e4 = blockIdx.x * 256 + threadIdx.x;   // 65536 float4 groups
    const float4 v = ((const float4*)hs)[e4];
    const __nv_bfloat16 h0 = __float2bfloat16(v.x), h1 = __float2bfloat16(v.y);
    const __nv_bfloat16 h2 = __float2bfloat16(v.z), h3 = __float2bfloat16(v.w);
    uint2 hw, lw;
    hw.x = pack2(h0, h1); hw.y = pack2(h2, h3);
    lw.x = pack2(__float2bfloat16(v.x - __bfloat162float(h0)),
                 __float2bfloat16(v.y - __bfloat162float(h1)));
    lw.y = pack2(__float2bfloat16(v.z - __bfloat162float(h2)),
                 __float2bfloat16(v.w - __bfloat162float(h3)));
    ((uint2*)g_Hh)[e4] = hw;
    ((uint2*)g_Hl)[e4] = lw;
}

// ---------------------------------------------------------------------------
// GEMM: Y[4096, 4096] = hs[4096, 64] @ Wr[64, 4096]
// split-bf16: hi*hi + hi*lo + lo*hi, fp32 accumulate via mma.sync (HMMA).
// CTA: 128 threads (4 warps), tile M=128 x N=64, full K=64. Grid 2048.
// ---------------------------------------------------------------------------
__global__ void __launch_bounds__(128) gemm_kernel() {
    __shared__ __align__(16) __nv_bfloat16 sAh[128 * 64];
    __shared__ __align__(16) __nv_bfloat16 sAl[128 * 64];
    __shared__ __align__(16) __nv_bfloat16 sBh[64 * 64];
    __shared__ __align__(16) __nv_bfloat16 sBl[64 * 64];

    const int tid = threadIdx.x, lane = tid & 31, w = tid >> 5;
    const int mb = blockIdx.x >> 6, nb = blockIdx.x & 63;
    const int m0 = mb * 128, n0 = nb * 64;

    // Load A tiles (preconverted bf16 hi/lo), swizzled stores.
    #pragma unroll
    for (int u = 0; u < 8; ++u) {
        const int idx = u * 128 + tid;          // uint4 index, 1024 per array
        const int r = idx >> 3, chunk = idx & 7;
        const int boff = r * 128 + ((chunk ^ (r & 7)) * 16);
        *(uint4*)((char*)sAh + boff) = ((const uint4*)(g_Hh + (size_t)(m0 + r) * HD))[chunk];
        *(uint4*)((char*)sAl + boff) = ((const uint4*)(g_Hl + (size_t)(m0 + r) * HD))[chunk];
    }
    // Load B tiles, swizzled.
    #pragma unroll
    for (int u = 0; u < 8; ++u) {
        const int idx = u * 128 + tid;          // uint2 index, 1024 total
        const int r = idx >> 4, q = idx & 15;
        const uint2 hv = ((const uint2*)(g_Wh + (size_t)r * YC + n0))[q];
        const uint2 lv = ((const uint2*)(g_Wl + (size_t)r * YC + n0))[q];
        const int chunk = q >> 1, half = q & 1;
        const int boff = r * 128 + ((chunk ^ (r & 7)) * 16) + half * 8;
        *(uint2*)((char*)sBh + boff) = hv;
        *(uint2*)((char*)sBl + boff) = lv;
    }
    __syncthreads();

    float acc[2][8][4];
    #pragma unroll
    for (int mt = 0; mt < 2; ++mt)
        #pragma unroll
        for (int nt = 0; nt < 8; ++nt)
            #pragma unroll
            for (int q = 0; q < 4; ++q) acc[mt][nt][q] = 0.0f;

    const uint32_t aB[3] = { smem_u32(sAh), smem_u32(sAh), smem_u32(sAl) };
    const uint32_t bB[3] = { smem_u32(sBh), smem_u32(sBl), smem_u32(sBh) };

    #pragma unroll
    for (int term = 0; term < 3; ++term) {
        #pragma unroll
        for (int kt = 0; kt < 4; ++kt) {
            uint32_t a[2][4], b[8][2];
            #pragma unroll
            for (int mt = 0; mt < 2; ++mt) {
                const int rr = w * 32 + mt * 16 + (lane & 15);
                const int cc = kt * 2 + (lane >> 4);
                ldsm_x4(a[mt], aB[term] + rr * 128 + ((cc ^ (rr & 7)) * 16));
            }
            #pragma unroll
            for (int nt = 0; nt < 8; ++nt) {
                const int kk = kt * 16 + (lane & 15);
                ldsm_x2t(b[nt], bB[term] + kk * 128 + ((nt ^ (kk & 7)) * 16));
            }
            #pragma unroll
            for (int mt = 0; mt < 2; ++mt)
                #pragma unroll
                for (int nt = 0; nt < 8; ++nt)
                    mma16816(acc[mt][nt], a[mt], b[nt]);
        }
    }

    // Store Y (fp32).
    #pragma unroll
    for (int mt = 0; mt < 2; ++mt) {
        const int row = m0 + w * 32 + mt * 16 + (lane >> 2);
        #pragma unroll
        for (int nt = 0; nt < 8; ++nt) {
            const int col = n0 + nt * 8 + (lane & 3) * 2;
            *(float2*)&g_Y[(size_t)row * YC + col]       = make_float2(acc[mt][nt][0], acc[mt][nt][1]);
            *(float2*)&g_Y[(size_t)(row + 8) * YC + col] = make_float2(acc[mt][nt][2], acc[mt][nt][3]);
        }
    }
}

// ---------------------------------------------------------------------------
// Gather: X[i,o] = sum over unmasked j of Y[j, cell(i,j)*64 + o]
// ---------------------------------------------------------------------------
__global__ void gather_kernel(const float* __restrict__ pos, float* __restrict__ X) {
    __shared__ int list[NPED];
    __shared__ int cnt;
    const int i = blockIdx.x, s = i >> 7, iloc = i & 127, tid = threadIdx.x;
    if (tid == 0) cnt = 0;
    __syncthreads();

    const float xi = pos[2 * i], yi = pos[2 * i + 1];
    const float tlx = xi - 1.0f, tly = yi + 1.0f, brx = xi + 1.0f, bry = yi - 1.0f;

    for (int j = tid; j < NPED; j += 64) {
        const float xj = pos[2 * (s * NPED + j)];
        const float yj = pos[2 * (s * NPED + j) + 1];
        const bool m = (xj <= tlx) || (yj >= tly) || (xj >= brx) || (yj <= bry) || (j == iloc);
        if (!m) {
            const int gx = (int)floorf((xj - tlx) * 4.0f);
            const int gy = (int)floorf((tly - yj) * 4.0f);
            const int p = atomicAdd(&cnt, 1);
            list[p] = (j << 8) | (gx + 8 * gy);
        }
    }
    __syncthreads();

    const float* Yf = g_Y + (size_t)s * NPED * YC;
    const int n = cnt;
    float a0 = 0.0f, a1 = 0.0f, a2 = 0.0f, a3 = 0.0f;
    int e = 0;
    for (; e + 4 <= n; e += 4) {
        const int e0 = list[e], e1 = list[e + 1], e2 = list[e + 2], e3 = list[e + 3];
        a0 += Yf[(size_t)(e0 >> 8) * YC + (e0 & 255) * 64 + tid];
        a1 += Yf[(size_t)(e1 >> 8) * YC + (e1 & 255) * 64 + tid];
        a2 += Yf[(size_t)(e2 >> 8) * YC + (e2 & 255) * 64 + tid];
        a3 += Yf[(size_t)(e3 >> 8) * YC + (e3 & 255) * 64 + tid];
    }
    for (; e < n; ++e) {
        const int e0 = list[e];
        a0 += Yf[(size_t)(e0 >> 8) * YC + (e0 & 255) * 64 + tid];
    }
    X[(size_t)i * NOUT + tid] = (a0 + a1) + (a2 + a3);
}

// ---------------------------------------------------------------------------
// BN stage 1: coalesced partial sums. Block b covers rows [b*32, b*32+32).
// ---------------------------------------------------------------------------
__global__ void red1_kernel(const float* __restrict__ X) {
    __shared__ float sm1[4][64], sm2[4][64];
    const int b = blockIdx.x, t = threadIdx.x;   // 128 blocks, 256 threads
    const int o = t & 63, g = t >> 6;
    float s = 0.0f, s2 = 0.0f;
    const float* base = X + (size_t)b * 32 * NOUT;
    #pragma unroll
    for (int r = g; r < 32; r += 4) {
        const float v = base[r * NOUT + o];
        s += v; s2 += v * v;
    }
    sm1[g][o] = s; sm2[g][o] = s2;
    __syncthreads();
    if (t < 64) {
        g_part[b * 128 + t]      = sm1[0][t] + sm1[1][t] + sm1[2][t] + sm1[3][t];
        g_part[b * 128 + 64 + t] = sm2[0][t] + sm2[1][t] + sm2[2][t] + sm2[3][t];
    }
}

// ---------------------------------------------------------------------------
// BN stage 2: finalize scale/shift. Bias b cancels in (x - mean).
// ---------------------------------------------------------------------------
__global__ void red2_kernel(const float* __restrict__ gamma,
                            const float* __restrict__ beta) {
    const int o = threadIdx.x;   // 64
    float s = 0.0f, s2 = 0.0f;
    #pragma unroll 4
    for (int p = 0; p < 128; ++p) {
        s  += g_part[p * 128 + o];
        s2 += g_part[p * 128 + 64 + o];
    }
    const float mean = s * (1.0f / NROWS);
    const float var  = s2 * (1.0f / NROWS) - mean * mean;
    const float sc = rsqrtf(var + 1e-5f) * gamma[o];
    g_scale[o] = sc;
    g_shift[o] = beta[o] - mean * sc;
}

__global__ void bn_apply(float* __restrict__ X) {
    const int idx = blockIdx.x * blockDim.x + threadIdx.x;   // float4 index
    float4 v = ((float4*)X)[idx];
    const int o = (idx * 4) & 63;
    v.x = fmaxf(fmaf(v.x, g_scale[o],     g_shift[o]),     0.0f);
    v.y = fmaxf(fmaf(v.y, g_scale[o + 1], g_shift[o + 1]), 0.0f);
    v.z = fmaxf(fmaf(v.z, g_scale[o + 2], g_shift[o + 2]), 0.0f);
    v.w = fmaxf(fmaf(v.w, g_scale[o + 3], g_shift[o + 3]), 0.0f);
    ((float4*)X)[idx] = v;
}

// ---------------------------------------------------------------------------
extern "C" void kernel_launch(void* const* d_in, const int* in_sizes, int n_in,
                              void* d_out, int out_size) {
    const float* hs    = (const float*)d_in[0];   // hidden_states [4096,64]
    const float* pos   = (const float*)d_in[1];   // all_pos       [4096,2]
    const float* Wm    = (const float*)d_in[2];   // W             [4096,64]
    // d_in[3] = b: cancels inside BatchNorm
    const float* gamma = (const float*)d_in[4];
    const float* beta  = (const float*)d_in[5];
    float* X = (float*)d_out;

    wprep_kernel<<<1024, 256>>>(Wm);
    hprep_kernel<<<256, 256>>>(hs);
    gemm_kernel<<<2048, 128>>>();
    gather_kernel<<<4096, 64>>>(pos, X);
    red1_kernel<<<128, 256>>>(X);
    red2_kernel<<<1, 64>>>(gamma, beta);
    bn_apply<<<256, 256>>>(X);
}

// round 5
// speedup vs baseline: 1.1702x; 1.1702x over previous
#include <cuda_runtime.h>
#include <cuda_fp16.h>
#include <math.h>
#include <stdint.h>

#define NPED  128
#define HD    64
#define NOUT  64
#define NROWS 4096
#define YC    4096      // Y columns = 64 cells * 64 out

// ---- scratch (no allocs allowed) ----
__device__ __align__(256) __half g_Y16[(size_t)NROWS * YC];    // 32 MB
__device__ __align__(256) __half g_Wh[64 * YC];                // Wr hi: [h][c*64+o]
__device__ __align__(256) __half g_Wl[64 * YC];                // Wr lo
__device__ __align__(256) __half g_H16[NROWS * HD];            // hs fp16
__device__ float g_part[128 * 2 * NOUT];                       // BN partials
__device__ float g_scale[NOUT];
__device__ float g_shift[NOUT];

// ---------------- helpers ----------------
__device__ __forceinline__ uint32_t smem_u32(const void* p) {
    uint32_t a;
    asm("{ .reg .u64 t; cvta.to.shared.u64 t, %1; cvt.u32.u64 %0, t; }" : "=r"(a) : "l"(p));
    return a;
}
__device__ __forceinline__ void ldsm_x4(uint32_t* a, uint32_t addr) {
    asm volatile("ldmatrix.sync.aligned.m8n8.x4.shared.b16 {%0,%1,%2,%3}, [%4];"
                 : "=r"(a[0]), "=r"(a[1]), "=r"(a[2]), "=r"(a[3]) : "r"(addr));
}
__device__ __forceinline__ void ldsm_x2t(uint32_t* b, uint32_t addr) {
    asm volatile("ldmatrix.sync.aligned.m8n8.x2.trans.shared.b16 {%0,%1}, [%2];"
                 : "=r"(b[0]), "=r"(b[1]) : "r"(addr));
}
__device__ __forceinline__ void mma16816(float* d, const uint32_t* a, const uint32_t* b) {
    asm volatile("mma.sync.aligned.m16n8k16.row.col.f32.f16.f16.f32 "
                 "{%0,%1,%2,%3}, {%4,%5,%6,%7}, {%8,%9}, {%0,%1,%2,%3};"
                 : "+f"(d[0]), "+f"(d[1]), "+f"(d[2]), "+f"(d[3])
                 : "r"(a[0]), "r"(a[1]), "r"(a[2]), "r"(a[3]), "r"(b[0]), "r"(b[1]));
}

// ---------------------------------------------------------------------------
// W prep: Wr[h][c*64+o] = W[c*64+h][o], split fp16 hi/lo. Coalesced read.
// ---------------------------------------------------------------------------
__global__ void wprep_kernel(const float* __restrict__ W) {
    const int e = blockIdx.x * 256 + threadIdx.x;   // 262144 total
    const float v = W[e];
    const __half hi = __float2half_rn(v);
    const __half lo = __float2half_rn(v - __half2float(hi));
    const int widx = ((e >> 6) & 63) * YC + (e >> 12) * 64 + (e & 63);
    g_Wh[widx] = hi;
    g_Wl[widx] = lo;
}

// ---------------------------------------------------------------------------
// hs prep: fp32 -> fp16 (single precision term on the A side).
// ---------------------------------------------------------------------------
__global__ void hprep_kernel(const float* __restrict__ hs) {
    const int e4 = blockIdx.x * 256 + threadIdx.x;   // 65536 float4 groups
    const float4 v = ((const float4*)hs)[e4];
    __half2 a = __floats2half2_rn(v.x, v.y);
    __half2 b = __floats2half2_rn(v.z, v.w);
    uint2 w;
    w.x = *(uint32_t*)&a;
    w.y = *(uint32_t*)&b;
    ((uint2*)g_H16)[e4] = w;
}

// ---------------------------------------------------------------------------
// GEMM: Y[4096, 4096] = hs16[4096, 64] @ (Wh + Wl)[64, 4096]
// 2-term fp16 (A single, B split), fp32 accumulate via mma.sync.
// CTA: 128 threads (4 warps), tile M=128 x N=64, full K=64. Grid 2048.
// ---------------------------------------------------------------------------
__global__ void __launch_bounds__(128) gemm_kernel() {
    __shared__ __align__(16) __half sA [128 * 64];
    __shared__ __align__(16) __half sBh[64 * 64];
    __shared__ __align__(16) __half sBl[64 * 64];

    const int tid = threadIdx.x, lane = tid & 31, w = tid >> 5;
    const int mb = blockIdx.x >> 6, nb = blockIdx.x & 63;
    const int m0 = mb * 128, n0 = nb * 64;

    // Load A tile (fp16), swizzled stores. 1024 uint4.
    #pragma unroll
    for (int u = 0; u < 8; ++u) {
        const int idx = u * 128 + tid;
        const int r = idx >> 3, chunk = idx & 7;
        const int boff = r * 128 + ((chunk ^ (r & 7)) * 16);
        *(uint4*)((char*)sA + boff) = ((const uint4*)(g_H16 + (size_t)(m0 + r) * HD))[chunk];
    }
    // Load B tiles (hi/lo), swizzled.
    #pragma unroll
    for (int u = 0; u < 8; ++u) {
        const int idx = u * 128 + tid;          // uint2 index, 1024 total
        const int r = idx >> 4, q = idx & 15;
        const uint2 hv = ((const uint2*)(g_Wh + (size_t)r * YC + n0))[q];
        const uint2 lv = ((const uint2*)(g_Wl + (size_t)r * YC + n0))[q];
        const int chunk = q >> 1, half = q & 1;
        const int boff = r * 128 + ((chunk ^ (r & 7)) * 16) + half * 8;
        *(uint2*)((char*)sBh + boff) = hv;
        *(uint2*)((char*)sBl + boff) = lv;
    }
    __syncthreads();

    float acc[2][8][4];
    #pragma unroll
    for (int mt = 0; mt < 2; ++mt)
        #pragma unroll
        for (int nt = 0; nt < 8; ++nt)
            #pragma unroll
            for (int q = 0; q < 4; ++q) acc[mt][nt][q] = 0.0f;

    const uint32_t aB  = smem_u32(sA);
    const uint32_t bBh = smem_u32(sBh);
    const uint32_t bBl = smem_u32(sBl);

    #pragma unroll
    for (int kt = 0; kt < 4; ++kt) {
        uint32_t a[2][4], bh[8][2], bl[8][2];
        #pragma unroll
        for (int mt = 0; mt < 2; ++mt) {
            const int rr = w * 32 + mt * 16 + (lane & 15);
            const int cc = kt * 2 + (lane >> 4);
            ldsm_x4(a[mt], aB + rr * 128 + ((cc ^ (rr & 7)) * 16));
        }
        #pragma unroll
        for (int nt = 0; nt < 8; ++nt) {
            const int kk = kt * 16 + (lane & 15);
            const int so = kk * 128 + ((nt ^ (kk & 7)) * 16);
            ldsm_x2t(bh[nt], bBh + so);
            ldsm_x2t(bl[nt], bBl + so);
        }
        #pragma unroll
        for (int mt = 0; mt < 2; ++mt)
            #pragma unroll
            for (int nt = 0; nt < 8; ++nt) {
                mma16816(acc[mt][nt], a[mt], bh[nt]);
                mma16816(acc[mt][nt], a[mt], bl[nt]);
            }
    }

    // Store Y (fp16).
    #pragma unroll
    for (int mt = 0; mt < 2; ++mt) {
        const int row = m0 + w * 32 + mt * 16 + (lane >> 2);
        #pragma unroll
        for (int nt = 0; nt < 8; ++nt) {
            const int col = n0 + nt * 8 + (lane & 3) * 2;
            const __half2 lo2 = __floats2half2_rn(acc[mt][nt][0], acc[mt][nt][1]);
            const __half2 hi2 = __floats2half2_rn(acc[mt][nt][2], acc[mt][nt][3]);
            *(__half2*)&g_Y16[(size_t)row * YC + col]       = lo2;
            *(__half2*)&g_Y16[(size_t)(row + 8) * YC + col] = hi2;
        }
    }
}

// ---------------------------------------------------------------------------
// Gather: X[i,o] = sum over unmasked j of Y[j, cell(i,j)*64 + o]
// ---------------------------------------------------------------------------
__global__ void gather_kernel(const float* __restrict__ pos, float* __restrict__ X) {
    __shared__ int list[NPED];
    __shared__ int cnt;
    const int i = blockIdx.x, s = i >> 7, iloc = i & 127, tid = threadIdx.x;
    if (tid == 0) cnt = 0;
    __syncthreads();

    const float xi = pos[2 * i], yi = pos[2 * i + 1];
    const float tlx = xi - 1.0f, tly = yi + 1.0f, brx = xi + 1.0f, bry = yi - 1.0f;

    for (int j = tid; j < NPED; j += 64) {
        const float xj = pos[2 * (s * NPED + j)];
        const float yj = pos[2 * (s * NPED + j) + 1];
        const bool m = (xj <= tlx) || (yj >= tly) || (xj >= brx) || (yj <= bry) || (j == iloc);
        if (!m) {
            const int gx = (int)floorf((xj - tlx) * 4.0f);
            const int gy = (int)floorf((tly - yj) * 4.0f);
            const int p = atomicAdd(&cnt, 1);
            list[p] = (j << 8) | (gx + 8 * gy);
        }
    }
    __syncthreads();

    const __half* Yf = g_Y16 + (size_t)s * NPED * YC;
    const int n = cnt;
    float a0 = 0.0f, a1 = 0.0f, a2 = 0.0f, a3 = 0.0f;
    int e = 0;
    for (; e + 4 <= n; e += 4) {
        const int e0 = list[e], e1 = list[e + 1], e2 = list[e + 2], e3 = list[e + 3];
        a0 += __half2float(Yf[(size_t)(e0 >> 8) * YC + (e0 & 255) * 64 + tid]);
        a1 += __half2float(Yf[(size_t)(e1 >> 8) * YC + (e1 & 255) * 64 + tid]);
        a2 += __half2float(Yf[(size_t)(e2 >> 8) * YC + (e2 & 255) * 64 + tid]);
        a3 += __half2float(Yf[(size_t)(e3 >> 8) * YC + (e3 & 255) * 64 + tid]);
    }
    for (; e < n; ++e) {
        const int e0 = list[e];
        a0 += __half2float(Yf[(size_t)(e0 >> 8) * YC + (e0 & 255) * 64 + tid]);
    }
    X[(size_t)i * NOUT + tid] = (a0 + a1) + (a2 + a3);
}

// ---------------------------------------------------------------------------
// BN stage 1: coalesced partial sums. Block b covers rows [b*32, b*32+32).
// ---------------------------------------------------------------------------
__global__ void red1_kernel(const float* __restrict__ X) {
    __shared__ float sm1[4][64], sm2[4][64];
    const int b = blockIdx.x, t = threadIdx.x;   // 128 blocks, 256 threads
    const int o = t & 63, g = t >> 6;
    float s = 0.0f, s2 = 0.0f;
    const float* base = X + (size_t)b * 32 * NOUT;
    #pragma unroll
    for (int r = g; r < 32; r += 4) {
        const float v = base[r * NOUT + o];
        s += v; s2 += v * v;
    }
    sm1[g][o] = s; sm2[g][o] = s2;
    __syncthreads();
    if (t < 64) {
        g_part[b * 128 + t]      = sm1[0][t] + sm1[1][t] + sm1[2][t] + sm1[3][t];
        g_part[b * 128 + 64 + t] = sm2[0][t] + sm2[1][t] + sm2[2][t] + sm2[3][t];
    }
}

// ---------------------------------------------------------------------------
// BN stage 2: finalize scale/shift. Bias b cancels in (x - mean).
// ---------------------------------------------------------------------------
__global__ void red2_kernel(const float* __restrict__ gamma,
                            const float* __restrict__ beta) {
    const int o = threadIdx.x;   // 64
    float s = 0.0f, s2 = 0.0f;
    #pragma unroll 4
    for (int p = 0; p < 128; ++p) {
        s  += g_part[p * 128 + o];
        s2 += g_part[p * 128 + 64 + o];
    }
    const float mean = s * (1.0f / NROWS);
    const float var  = s2 * (1.0f / NROWS) - mean * mean;
    const float sc = rsqrtf(var + 1e-5f) * gamma[o];
    g_scale[o] = sc;
    g_shift[o] = beta[o] - mean * sc;
}

__global__ void bn_apply(float* __restrict__ X) {
    const int idx = blockIdx.x * blockDim.x + threadIdx.x;   // float4 index
    float4 v = ((float4*)X)[idx];
    const int o = (idx * 4) & 63;
    v.x = fmaxf(fmaf(v.x, g_scale[o],     g_shift[o]),     0.0f);
    v.y = fmaxf(fmaf(v.y, g_scale[o + 1], g_shift[o + 1]), 0.0f);
    v.z = fmaxf(fmaf(v.z, g_scale[o + 2], g_shift[o + 2]), 0.0f);
    v.w = fmaxf(fmaf(v.w, g_scale[o + 3], g_shift[o + 3]), 0.0f);
    ((float4*)X)[idx] = v;
}

// ---------------------------------------------------------------------------
extern "C" void kernel_launch(void* const* d_in, const int* in_sizes, int n_in,
                              void* d_out, int out_size) {
    const float* hs    = (const float*)d_in[0];   // hidden_states [4096,64]
    const float* pos   = (const float*)d_in[1];   // all_pos       [4096,2]
    const float* Wm    = (const float*)d_in[2];   // W             [4096,64]
    // d_in[3] = b: cancels inside BatchNorm
    const float* gamma = (const float*)d_in[4];
    const float* beta  = (const float*)d_in[5];
    float* X = (float*)d_out;

    wprep_kernel<<<1024, 256>>>(Wm);
    hprep_kernel<<<256, 256>>>(hs);
    gemm_kernel<<<2048, 128>>>();
    gather_kernel<<<4096, 64>>>(pos, X);
    red1_kernel<<<128, 256>>>(X);
    red2_kernel<<<1, 64>>>(gamma, beta);
    bn_apply<<<256, 256>>>(X);
}

// round 6
// speedup vs baseline: 1.2941x; 1.1059x over previous
#include <cuda_runtime.h>
#include <cuda_fp16.h>
#include <math.h>
#include <stdint.h>

#define NPED  128
#define HD    64
#define NOUT  64
#define NROWS 4096
#define YC    4096      // Y columns = 64 cells * 64 out

// ---- scratch (no allocs allowed) ----
__device__ __align__(256) __half g_Y16[(size_t)NROWS * YC];    // 32 MB
__device__ __align__(256) __half g_W16[64 * YC];               // Wr: [h][c*64+o]
__device__ __align__(256) __half g_H16[NROWS * HD];            // hs fp16
__device__ float g_part[128 * 2 * NOUT];                       // BN partials
__device__ float g_scale[NOUT];
__device__ float g_shift[NOUT];

// ---------------- helpers ----------------
__device__ __forceinline__ uint32_t smem_u32(const void* p) {
    uint32_t a;
    asm("{ .reg .u64 t; cvta.to.shared.u64 t, %1; cvt.u32.u64 %0, t; }" : "=r"(a) : "l"(p));
    return a;
}
__device__ __forceinline__ void ldsm_x4(uint32_t* a, uint32_t addr) {
    asm volatile("ldmatrix.sync.aligned.m8n8.x4.shared.b16 {%0,%1,%2,%3}, [%4];"
                 : "=r"(a[0]), "=r"(a[1]), "=r"(a[2]), "=r"(a[3]) : "r"(addr));
}
__device__ __forceinline__ void ldsm_x4t(uint32_t* b, uint32_t addr) {
    asm volatile("ldmatrix.sync.aligned.m8n8.x4.trans.shared.b16 {%0,%1,%2,%3}, [%4];"
                 : "=r"(b[0]), "=r"(b[1]), "=r"(b[2]), "=r"(b[3]) : "r"(addr));
}
__device__ __forceinline__ void mma16816(float* d, const uint32_t* a, const uint32_t* b) {
    asm volatile("mma.sync.aligned.m16n8k16.row.col.f32.f16.f16.f32 "
                 "{%0,%1,%2,%3}, {%4,%5,%6,%7}, {%8,%9}, {%0,%1,%2,%3};"
                 : "+f"(d[0]), "+f"(d[1]), "+f"(d[2]), "+f"(d[3])
                 : "r"(a[0]), "r"(a[1]), "r"(a[2]), "r"(a[3]), "r"(b[0]), "r"(b[1]));
}

// ---------------------------------------------------------------------------
// W prep: Wr[h][c*64+o] = fp16(W[c*64+h][o]). Coalesced read.
// ---------------------------------------------------------------------------
__global__ void wprep_kernel(const float* __restrict__ W) {
    const int e = blockIdx.x * 256 + threadIdx.x;   // 262144 total
    const int widx = ((e >> 6) & 63) * YC + (e >> 12) * 64 + (e & 63);
    g_W16[widx] = __float2half_rn(W[e]);
}

// ---------------------------------------------------------------------------
// hs prep: fp32 -> fp16.
// ---------------------------------------------------------------------------
__global__ void hprep_kernel(const float* __restrict__ hs) {
    const int e4 = blockIdx.x * 256 + threadIdx.x;   // 65536 float4 groups
    const float4 v = ((const float4*)hs)[e4];
    __half2 a = __floats2half2_rn(v.x, v.y);
    __half2 b = __floats2half2_rn(v.z, v.w);
    uint2 w;
    w.x = *(uint32_t*)&a;
    w.y = *(uint32_t*)&b;
    ((uint2*)g_H16)[e4] = w;
}

// ---------------------------------------------------------------------------
// GEMM: Y[4096, 4096] = hs16[4096, 64] @ W16[64, 4096], fp32 accum HMMA.
// CTA: 128 threads (4 warps), tile M=128 x N=64, full K=64. Grid 2048.
// ---------------------------------------------------------------------------
__global__ void __launch_bounds__(128) gemm_kernel() {
    __shared__ __align__(16) __half sA[128 * 64];
    __shared__ __align__(16) __half sB[64 * 64];

    const int tid = threadIdx.x, lane = tid & 31, w = tid >> 5;
    const int mb = blockIdx.x >> 6, nb = blockIdx.x & 63;
    const int m0 = mb * 128, n0 = nb * 64;

    // Load A tile (fp16), swizzled stores. 1024 uint4.
    #pragma unroll
    for (int u = 0; u < 8; ++u) {
        const int idx = u * 128 + tid;
        const int r = idx >> 3, chunk = idx & 7;
        const int boff = r * 128 + ((chunk ^ (r & 7)) * 16);
        *(uint4*)((char*)sA + boff) = ((const uint4*)(g_H16 + (size_t)(m0 + r) * HD))[chunk];
    }
    // Load B tile, swizzled. 512 uint4.
    #pragma unroll
    for (int u = 0; u < 4; ++u) {
        const int idx = u * 128 + tid;
        const int r = idx >> 3, chunk = idx & 7;
        const int boff = r * 128 + ((chunk ^ (r & 7)) * 16);
        *(uint4*)((char*)sB + boff) = ((const uint4*)(g_W16 + (size_t)r * YC + n0))[chunk];
    }
    __syncthreads();

    float acc[2][8][4];
    #pragma unroll
    for (int mt = 0; mt < 2; ++mt)
        #pragma unroll
        for (int nt = 0; nt < 8; ++nt)
            #pragma unroll
            for (int q = 0; q < 4; ++q) acc[mt][nt][q] = 0.0f;

    const uint32_t aB = smem_u32(sA);
    const uint32_t bB = smem_u32(sB);

    #pragma unroll
    for (int kt = 0; kt < 4; ++kt) {
        uint32_t a[2][4], b[8][2];
        #pragma unroll
        for (int mt = 0; mt < 2; ++mt) {
            const int rr = w * 32 + mt * 16 + (lane & 15);
            const int cc = kt * 2 + (lane >> 4);
            ldsm_x4(a[mt], aB + rr * 128 + ((cc ^ (rr & 7)) * 16));
        }
        // B fragments: x4.trans loads 4 8x8 mats -> two n8 blocks (2p, 2p+1)
        #pragma unroll
        for (int p = 0; p < 4; ++p) {
            const int g = lane >> 3;                       // 0..3
            const int row = kt * 16 + (g & 1) * 8 + (lane & 7);
            const int cchunk = p * 2 + (g >> 1);
            uint32_t bb[4];
            ldsm_x4t(bb, bB + row * 128 + ((cchunk ^ (row & 7)) * 16));
            b[2 * p][0] = bb[0]; b[2 * p][1] = bb[1];
            b[2 * p + 1][0] = bb[2]; b[2 * p + 1][1] = bb[3];
        }
        #pragma unroll
        for (int mt = 0; mt < 2; ++mt)
            #pragma unroll
            for (int nt = 0; nt < 8; ++nt)
                mma16816(acc[mt][nt], a[mt], b[nt]);
    }

    // Store Y (fp16).
    #pragma unroll
    for (int mt = 0; mt < 2; ++mt) {
        const int row = m0 + w * 32 + mt * 16 + (lane >> 2);
        #pragma unroll
        for (int nt = 0; nt < 8; ++nt) {
            const int col = n0 + nt * 8 + (lane & 3) * 2;
            const __half2 lo2 = __floats2half2_rn(acc[mt][nt][0], acc[mt][nt][1]);
            const __half2 hi2 = __floats2half2_rn(acc[mt][nt][2], acc[mt][nt][3]);
            *(__half2*)&g_Y16[(size_t)row * YC + col]       = lo2;
            *(__half2*)&g_Y16[(size_t)(row + 8) * YC + col] = hi2;
        }
    }
}

// ---------------------------------------------------------------------------
// Gather: X[i,o] = sum over unmasked j of Y[j, cell(i,j)*64 + o]
// 128 threads: two o-groups stride the entry list (2x MLP). Byte offsets
// precomputed in the list to kill the address-IMAD chain.
// ---------------------------------------------------------------------------
__global__ void __launch_bounds__(128) gather_kernel(const float* __restrict__ pos,
                                                     float* __restrict__ X) {
    __shared__ int list[NPED];
    __shared__ int cnt;
    __shared__ float xch[64];
    const int i = blockIdx.x, s = i >> 7, iloc = i & 127;
    const int tid = threadIdx.x, o = tid & 63, grp = tid >> 6;
    if (tid == 0) cnt = 0;
    __syncthreads();

    const float xi = pos[2 * i], yi = pos[2 * i + 1];
    const float tlx = xi - 1.0f, tly = yi + 1.0f, brx = xi + 1.0f, bry = yi - 1.0f;

    {   // one j per thread
        const int j = tid;
        const float xj = pos[2 * (s * NPED + j)];
        const float yj = pos[2 * (s * NPED + j) + 1];
        const bool m = (xj <= tlx) || (yj >= tly) || (xj >= brx) || (yj <= bry) || (j == iloc);
        if (!m) {
            const int gx = (int)floorf((xj - tlx) * 4.0f);
            const int gy = (int)floorf((tly - yj) * 4.0f);
            const int p = atomicAdd(&cnt, 1);
            list[p] = j * 8192 + (gx + 8 * gy) * 128;      // byte offset into Y frame
        }
    }
    __syncthreads();

    const char* Yf = (const char*)(g_Y16 + (size_t)s * NPED * YC) + o * 2;
    const int n = cnt;
    float a0 = 0.0f, a1 = 0.0f, a2 = 0.0f, a3 = 0.0f;
    int e = grp;
    for (; e + 6 < n; e += 8) {
        const int o0 = list[e], o1 = list[e + 2], o2 = list[e + 4], o3 = list[e + 6];
        a0 += __half2float(*(const __half*)(Yf + o0));
        a1 += __half2float(*(const __half*)(Yf + o1));
        a2 += __half2float(*(const __half*)(Yf + o2));
        a3 += __half2float(*(const __half*)(Yf + o3));
    }
    for (; e < n; e += 2)
        a0 += __half2float(*(const __half*)(Yf + list[e]));
    const float part = (a0 + a1) + (a2 + a3);

    if (grp == 1) xch[o] = part;
    __syncthreads();
    if (grp == 0) X[(size_t)i * NOUT + o] = part + xch[o];
}

// ---------------------------------------------------------------------------
// BN stage 1: coalesced partial sums. Block b covers rows [b*32, b*32+32).
// ---------------------------------------------------------------------------
__global__ void red1_kernel(const float* __restrict__ X) {
    __shared__ float sm1[4][64], sm2[4][64];
    const int b = blockIdx.x, t = threadIdx.x;   // 128 blocks, 256 threads
    const int o = t & 63, g = t >> 6;
    float s = 0.0f, s2 = 0.0f;
    const float* base = X + (size_t)b * 32 * NOUT;
    #pragma unroll
    for (int r = g; r < 32; r += 4) {
        const float v = base[r * NOUT + o];
        s += v; s2 += v * v;
    }
    sm1[g][o] = s; sm2[g][o] = s2;
    __syncthreads();
    if (t < 64) {
        g_part[b * 128 + t]      = sm1[0][t] + sm1[1][t] + sm1[2][t] + sm1[3][t];
        g_part[b * 128 + 64 + t] = sm2[0][t] + sm2[1][t] + sm2[2][t] + sm2[3][t];
    }
}

// ---------------------------------------------------------------------------
// BN stage 2: finalize scale/shift. Bias b cancels in (x - mean).
// ---------------------------------------------------------------------------
__global__ void red2_kernel(const float* __restrict__ gamma,
                            const float* __restrict__ beta) {
    const int o = threadIdx.x;   // 64
    float s = 0.0f, s2 = 0.0f;
    #pragma unroll 4
    for (int p = 0; p < 128; ++p) {
        s  += g_part[p * 128 + o];
        s2 += g_part[p * 128 + 64 + o];
    }
    const float mean = s * (1.0f / NROWS);
    const float var  = s2 * (1.0f / NROWS) - mean * mean;
    const float sc = rsqrtf(var + 1e-5f) * gamma[o];
    g_scale[o] = sc;
    g_shift[o] = beta[o] - mean * sc;
}

__global__ void bn_apply(float* __restrict__ X) {
    const int idx = blockIdx.x * blockDim.x + threadIdx.x;   // float4 index
    float4 v = ((float4*)X)[idx];
    const int o = (idx * 4) & 63;
    v.x = fmaxf(fmaf(v.x, g_scale[o],     g_shift[o]),     0.0f);
    v.y = fmaxf(fmaf(v.y, g_scale[o + 1], g_shift[o + 1]), 0.0f);
    v.z = fmaxf(fmaf(v.z, g_scale[o + 2], g_shift[o + 2]), 0.0f);
    v.w = fmaxf(fmaf(v.w, g_scale[o + 3], g_shift[o + 3]), 0.0f);
    ((float4*)X)[idx] = v;
}

// ---------------------------------------------------------------------------
extern "C" void kernel_launch(void* const* d_in, const int* in_sizes, int n_in,
                              void* d_out, int out_size) {
    const float* hs    = (const float*)d_in[0];   // hidden_states [4096,64]
    const float* pos   = (const float*)d_in[1];   // all_pos       [4096,2]
    const float* Wm    = (const float*)d_in[2];   // W             [4096,64]
    // d_in[3] = b: cancels inside BatchNorm
    const float* gamma = (const float*)d_in[4];
    const float* beta  = (const float*)d_in[5];
    float* X = (float*)d_out;

    wprep_kernel<<<1024, 256>>>(Wm);
    hprep_kernel<<<256, 256>>>(hs);
    gemm_kernel<<<2048, 128>>>();
    gather_kernel<<<4096, 128>>>(pos, X);
    red1_kernel<<<128, 256>>>(X);
    red2_kernel<<<1, 64>>>(gamma, beta);
    bn_apply<<<256, 256>>>(X);
}

// round 7
// speedup vs baseline: 1.4194x; 1.0968x over previous
#include <cuda_runtime.h>
#include <cuda_fp16.h>
#include <math.h>
#include <stdint.h>

#define NPED  128
#define HD    64
#define NOUT  64
#define NROWS 4096
#define YC    4096      // Y columns = 64 cells * 64 out

// ---- scratch (no allocs allowed) ----
__device__ __align__(256) __half g_Y16[(size_t)NROWS * YC];    // 32 MB
__device__ __align__(256) __half g_W16[64 * YC];               // Wr: [h][c*64+o]
__device__ __align__(256) __half g_H16[NROWS * HD];            // hs fp16
__device__ float g_part[128 * 2 * NOUT];                       // BN partials
__device__ float g_scale[NOUT];
__device__ float g_shift[NOUT];

// ---------------- helpers ----------------
__device__ __forceinline__ uint32_t smem_u32(const void* p) {
    uint32_t a;
    asm("{ .reg .u64 t; cvta.to.shared.u64 t, %1; cvt.u32.u64 %0, t; }" : "=r"(a) : "l"(p));
    return a;
}
__device__ __forceinline__ void cpa16(uint32_t dst, const void* src) {
    asm volatile("cp.async.cg.shared.global [%0], [%1], 16;" :: "r"(dst), "l"(src));
}
__device__ __forceinline__ void cp_commit_wait0() {
    asm volatile("cp.async.commit_group;" ::: "memory");
    asm volatile("cp.async.wait_group 0;" ::: "memory");
}
__device__ __forceinline__ void ldsm_x4(uint32_t* a, uint32_t addr) {
    asm volatile("ldmatrix.sync.aligned.m8n8.x4.shared.b16 {%0,%1,%2,%3}, [%4];"
                 : "=r"(a[0]), "=r"(a[1]), "=r"(a[2]), "=r"(a[3]) : "r"(addr));
}
__device__ __forceinline__ void ldsm_x4t(uint32_t* b, uint32_t addr) {
    asm volatile("ldmatrix.sync.aligned.m8n8.x4.trans.shared.b16 {%0,%1,%2,%3}, [%4];"
                 : "=r"(b[0]), "=r"(b[1]), "=r"(b[2]), "=r"(b[3]) : "r"(addr));
}
__device__ __forceinline__ void mma16816(float* d, const uint32_t* a, const uint32_t* b) {
    asm volatile("mma.sync.aligned.m16n8k16.row.col.f32.f16.f16.f32 "
                 "{%0,%1,%2,%3}, {%4,%5,%6,%7}, {%8,%9}, {%0,%1,%2,%3};"
                 : "+f"(d[0]), "+f"(d[1]), "+f"(d[2]), "+f"(d[3])
                 : "r"(a[0]), "r"(a[1]), "r"(a[2]), "r"(a[3]), "r"(b[0]), "r"(b[1]));
}

// ---------------------------------------------------------------------------
// W prep: Wr[h][c*64+o] = fp16(W[c*64+h][o]). Coalesced read.
// ---------------------------------------------------------------------------
__global__ void wprep_kernel(const float* __restrict__ W) {
    const int e = blockIdx.x * 256 + threadIdx.x;   // 262144 total
    const int widx = ((e >> 6) & 63) * YC + (e >> 12) * 64 + (e & 63);
    g_W16[widx] = __float2half_rn(W[e]);
}

// ---------------------------------------------------------------------------
// hs prep: fp32 -> fp16.
// ---------------------------------------------------------------------------
__global__ void hprep_kernel(const float* __restrict__ hs) {
    const int e4 = blockIdx.x * 256 + threadIdx.x;   // 65536 float4 groups
    const float4 v = ((const float4*)hs)[e4];
    __half2 a = __floats2half2_rn(v.x, v.y);
    __half2 b = __floats2half2_rn(v.z, v.w);
    uint2 w;
    w.x = *(uint32_t*)&a;
    w.y = *(uint32_t*)&b;
    ((uint2*)g_H16)[e4] = w;
}

// ---------------------------------------------------------------------------
// GEMM: Y[4096, 4096] = hs16[4096, 64] @ W16[64, 4096], fp32 accum HMMA.
// CTA: 256 threads (8 warps), tile M=128 x N=128, full K=64. Grid 1024.
// Warp (wm = w&3, wn = w>>2): M=32 x N=64 sub-tile. cp.async loads.
// ---------------------------------------------------------------------------
__global__ void __launch_bounds__(256) gemm_kernel() {
    __shared__ __align__(16) __half sA[128 * 64];       // 16 KB
    __shared__ __align__(16) __half sB[2][64 * 64];     // 2 x 8 KB, [k][n0..63]

    const int tid = threadIdx.x, lane = tid & 31, w = tid >> 5;
    const int wm = w & 3, wn = w >> 2;
    const int mb = blockIdx.x >> 5, nb = blockIdx.x & 31;
    const int m0 = mb * 128, n0 = nb * 128;

    const uint32_t aBase = smem_u32(sA);
    const uint32_t bBase0 = smem_u32(sB[0]);

    // A tile: 1024 uint4 (16 KB), 4 per thread, swizzled.
    #pragma unroll
    for (int u = 0; u < 4; ++u) {
        const int idx = u * 256 + tid;
        const int r = idx >> 3, chunk = idx & 7;
        const int boff = r * 128 + ((chunk ^ (r & 7)) * 16);
        cpa16(aBase + boff, g_H16 + (size_t)(m0 + r) * HD + chunk * 8);
    }
    // B tiles: two 64x64 halves of the N=128 stripe. 1024 uint4 total.
    #pragma unroll
    for (int u = 0; u < 4; ++u) {
        const int idx = u * 256 + tid;
        const int h = idx >> 9, i2 = idx & 511;
        const int r = i2 >> 3, chunk = i2 & 7;
        const int boff = h * 8192 + r * 128 + ((chunk ^ (r & 7)) * 16);
        cpa16(bBase0 + boff, g_W16 + (size_t)r * YC + n0 + h * 64 + chunk * 8);
    }
    cp_commit_wait0();
    __syncthreads();

    float acc[2][8][4];
    #pragma unroll
    for (int mt = 0; mt < 2; ++mt)
        #pragma unroll
        for (int nt = 0; nt < 8; ++nt)
            #pragma unroll
            for (int q = 0; q < 4; ++q) acc[mt][nt][q] = 0.0f;

    const uint32_t bB = bBase0 + wn * 8192;

    #pragma unroll
    for (int kt = 0; kt < 4; ++kt) {
        uint32_t a[2][4], b[8][2];
        #pragma unroll
        for (int mt = 0; mt < 2; ++mt) {
            const int rr = wm * 32 + mt * 16 + (lane & 15);
            const int cc = kt * 2 + (lane >> 4);
            ldsm_x4(a[mt], aBase + rr * 128 + ((cc ^ (rr & 7)) * 16));
        }
        #pragma unroll
        for (int p = 0; p < 4; ++p) {
            const int g = lane >> 3;
            const int row = kt * 16 + (g & 1) * 8 + (lane & 7);
            const int cchunk = p * 2 + (g >> 1);
            uint32_t bb[4];
            ldsm_x4t(bb, bB + row * 128 + ((cchunk ^ (row & 7)) * 16));
            b[2 * p][0] = bb[0]; b[2 * p][1] = bb[1];
            b[2 * p + 1][0] = bb[2]; b[2 * p + 1][1] = bb[3];
        }
        #pragma unroll
        for (int mt = 0; mt < 2; ++mt)
            #pragma unroll
            for (int nt = 0; nt < 8; ++nt)
                mma16816(acc[mt][nt], a[mt], b[nt]);
    }

    // Store Y (fp16).
    #pragma unroll
    for (int mt = 0; mt < 2; ++mt) {
        const int row = m0 + wm * 32 + mt * 16 + (lane >> 2);
        #pragma unroll
        for (int nt = 0; nt < 8; ++nt) {
            const int col = n0 + wn * 64 + nt * 8 + (lane & 3) * 2;
            const __half2 lo2 = __floats2half2_rn(acc[mt][nt][0], acc[mt][nt][1]);
            const __half2 hi2 = __floats2half2_rn(acc[mt][nt][2], acc[mt][nt][3]);
            *(__half2*)&g_Y16[(size_t)row * YC + col]       = lo2;
            *(__half2*)&g_Y16[(size_t)(row + 8) * YC + col] = hi2;
        }
    }
}

// ---------------------------------------------------------------------------
// Gather: X[i,o] = sum over unmasked j of Y[j, cell(i,j)*64 + o]
// 64 threads = 2 warps; lane covers o = 2*lane, 2*lane+1 (half2 load):
// one 128B warp-load per entry. Warps stride entries by 2, 4-deep unroll.
// ---------------------------------------------------------------------------
__global__ void __launch_bounds__(64) gather_kernel(const float* __restrict__ pos,
                                                    float* __restrict__ X) {
    __shared__ int list[NPED];
    __shared__ int cnt;
    __shared__ float2 xch[32];
    const int i = blockIdx.x, s = i >> 7, iloc = i & 127;
    const int tid = threadIdx.x, lane = tid & 31, w = tid >> 5;
    if (tid == 0) cnt = 0;
    __syncthreads();

    const float xi = pos[2 * i], yi = pos[2 * i + 1];
    const float tlx = xi - 1.0f, tly = yi + 1.0f, brx = xi + 1.0f, bry = yi - 1.0f;

    #pragma unroll
    for (int jj = 0; jj < 2; ++jj) {
        const int j = tid + jj * 64;
        const float xj = pos[2 * (s * NPED + j)];
        const float yj = pos[2 * (s * NPED + j) + 1];
        const bool m = (xj <= tlx) || (yj >= tly) || (xj >= brx) || (yj <= bry) || (j == iloc);
        if (!m) {
            const int gx = (int)floorf((xj - tlx) * 4.0f);
            const int gy = (int)floorf((tly - yj) * 4.0f);
            const int p = atomicAdd(&cnt, 1);
            list[p] = j * 8192 + (gx + 8 * gy) * 128;      // byte offset into Y frame
        }
    }
    __syncthreads();

    const char* Yf = (const char*)(g_Y16 + (size_t)s * NPED * YC) + lane * 4;
    const int n = cnt;
    float2 a0 = make_float2(0.f, 0.f), a1 = a0, a2 = a0, a3 = a0;
    int e = w;
    for (; e + 6 < n; e += 8) {
        const int o0 = list[e], o1 = list[e + 2], o2 = list[e + 4], o3 = list[e + 6];
        const float2 v0 = __half22float2(*(const __half2*)(Yf + o0));
        const float2 v1 = __half22float2(*(const __half2*)(Yf + o1));
        const float2 v2 = __half22float2(*(const __half2*)(Yf + o2));
        const float2 v3 = __half22float2(*(const __half2*)(Yf + o3));
        a0.x += v0.x; a0.y += v0.y;
        a1.x += v1.x; a1.y += v1.y;
        a2.x += v2.x; a2.y += v2.y;
        a3.x += v3.x; a3.y += v3.y;
    }
    for (; e < n; e += 2) {
        const float2 v = __half22float2(*(const __half2*)(Yf + list[e]));
        a0.x += v.x; a0.y += v.y;
    }
    float2 part;
    part.x = (a0.x + a1.x) + (a2.x + a3.x);
    part.y = (a0.y + a1.y) + (a2.y + a3.y);

    if (w == 1) xch[lane] = part;
    __syncthreads();
    if (w == 0) {
        const float2 t = xch[lane];
        part.x += t.x; part.y += t.y;
        *(float2*)&X[(size_t)i * NOUT + 2 * lane] = part;
    }
}

// ---------------------------------------------------------------------------
// BN stage 1: coalesced partial sums. Block b covers rows [b*32, b*32+32).
// ---------------------------------------------------------------------------
__global__ void red1_kernel(const float* __restrict__ X) {
    __shared__ float sm1[4][64], sm2[4][64];
    const int b = blockIdx.x, t = threadIdx.x;   // 128 blocks, 256 threads
    const int o = t & 63, g = t >> 6;
    float s = 0.0f, s2 = 0.0f;
    const float* base = X + (size_t)b * 32 * NOUT;
    #pragma unroll
    for (int r = g; r < 32; r += 4) {
        const float v = base[r * NOUT + o];
        s += v; s2 += v * v;
    }
    sm1[g][o] = s; sm2[g][o] = s2;
    __syncthreads();
    if (t < 64) {
        g_part[b * 128 + t]      = sm1[0][t] + sm1[1][t] + sm1[2][t] + sm1[3][t];
        g_part[b * 128 + 64 + t] = sm2[0][t] + sm2[1][t] + sm2[2][t] + sm2[3][t];
    }
}

// ---------------------------------------------------------------------------
// BN stage 2: finalize scale/shift. Bias b cancels in (x - mean).
// ---------------------------------------------------------------------------
__global__ void red2_kernel(const float* __restrict__ gamma,
                            const float* __restrict__ beta) {
    const int o = threadIdx.x;   // 64
    float s = 0.0f, s2 = 0.0f;
    #pragma unroll 4
    for (int p = 0; p < 128; ++p) {
        s  += g_part[p * 128 + o];
        s2 += g_part[p * 128 + 64 + o];
    }
    const float mean = s * (1.0f / NROWS);
    const float var  = s2 * (1.0f / NROWS) - mean * mean;
    const float sc = rsqrtf(var + 1e-5f) * gamma[o];
    g_scale[o] = sc;
    g_shift[o] = beta[o] - mean * sc;
}

__global__ void bn_apply(float* __restrict__ X) {
    const int idx = blockIdx.x * blockDim.x + threadIdx.x;   // float4 index
    float4 v = ((float4*)X)[idx];
    const int o = (idx * 4) & 63;
    v.x = fmaxf(fmaf(v.x, g_scale[o],     g_shift[o]),     0.0f);
    v.y = fmaxf(fmaf(v.y, g_scale[o + 1], g_shift[o + 1]), 0.0f);
    v.z = fmaxf(fmaf(v.z, g_scale[o + 2], g_shift[o + 2]), 0.0f);
    v.w = fmaxf(fmaf(v.w, g_scale[o + 3], g_shift[o + 3]), 0.0f);
    ((float4*)X)[idx] = v;
}

// ---------------------------------------------------------------------------
extern "C" void kernel_launch(void* const* d_in, const int* in_sizes, int n_in,
                              void* d_out, int out_size) {
    const float* hs    = (const float*)d_in[0];   // hidden_states [4096,64]
    const float* pos   = (const float*)d_in[1];   // all_pos       [4096,2]
    const float* Wm    = (const float*)d_in[2];   // W             [4096,64]
    // d_in[3] = b: cancels inside BatchNorm
    const float* gamma = (const float*)d_in[4];
    const float* beta  = (const float*)d_in[5];
    float* X = (float*)d_out;

    wprep_kernel<<<1024, 256>>>(Wm);
    hprep_kernel<<<256, 256>>>(hs);
    gemm_kernel<<<1024, 256>>>();
    gather_kernel<<<4096, 64>>>(pos, X);
    red1_kernel<<<128, 256>>>(X);
    red2_kernel<<<1, 64>>>(gamma, beta);
    bn_apply<<<256, 256>>>(X);
}